// round 3
// baseline (speedup 1.0000x reference)
#include <cuda_runtime.h>
#include <cstdint>

// Problem constants (from reference)
#define NPTS 200000
#define NCLS 20
#define NPROP 256
#define NPAIR 400000
#define THRESH 100   // CLUSTER_PROPOSE_POINTS

// Derived
#define WPP (NPTS / 32)                 // 6250 words per proposal
#define WORDS ((size_t)NPROP * WPP)     // 1,600,000 words total

// Output layout (float32, concatenated in return order)
#define OFF_SCORES  ((size_t)0)
#define OFF_MASKS   ((size_t)256)
#define OFF_CLASSES ((size_t)(256 + (size_t)NPROP * NPTS))
#define OFF_BIAS    (OFF_CLASSES + 256)
#define OFF_PROBS   (OFF_BIAS + (size_t)NPTS * 3)

// Scratch (device globals: allocation-free)
__device__ unsigned int g_bits[WORDS];          // 6.4 MB dedupe bitmask
__device__ int   g_rep[NPROP];
__device__ int   g_count[NPROP];
__device__ float g_score[NPROP];
__device__ int   g_inst[NPROP];
__device__ int   g_flag[NPROP];
__device__ int   g_segpred[NPTS];

// K1: zero bitmask, init per-proposal scratch, copy bias passthrough (float4)
__global__ void k_init(const float* __restrict__ bias, float* __restrict__ bias_out) {
    size_t t = (size_t)blockIdx.x * blockDim.x + threadIdx.x;
    if (t < WORDS) g_bits[t] = 0u;
    if (t < NPROP) {
        g_rep[t]   = 0x7FFFFFFF;
        g_count[t] = 0;
        g_score[t] = 0.0f;
    }
    // bias copy: 600000 floats = 150000 float4
    if (t < (size_t)(NPTS * 3 / 4)) {
        const float4* src = (const float4*)bias;
        float4* dst = (float4*)bias_out;
        dst[t] = src[t];
    }
}

// K2: per-point softmax + argmax; write probs region and segpred
__global__ void k_softmax(const float* __restrict__ logit,
                          float* __restrict__ probs_out) {
    int n = blockIdx.x * blockDim.x + threadIdx.x;
    if (n >= NPTS) return;
    const float4* lp = (const float4*)(logit + (size_t)n * NCLS);
    float v[NCLS];
#pragma unroll
    for (int i = 0; i < 5; i++) {
        float4 q = lp[i];
        v[4 * i + 0] = q.x; v[4 * i + 1] = q.y;
        v[4 * i + 2] = q.z; v[4 * i + 3] = q.w;
    }
    float m = v[0]; int am = 0;
#pragma unroll
    for (int i = 1; i < NCLS; i++) {
        if (v[i] > m) { m = v[i]; am = i; }
    }
    float e[NCLS];
    float s = 0.0f;
#pragma unroll
    for (int i = 0; i < NCLS; i++) { e[i] = __expf(v[i] - m); s += e[i]; }
    float inv = 1.0f / s;
    float4* pp = (float4*)(probs_out + (size_t)n * NCLS);
#pragma unroll
    for (int i = 0; i < 5; i++) {
        float4 q;
        q.x = e[4 * i + 0] * inv; q.y = e[4 * i + 1] * inv;
        q.z = e[4 * i + 2] * inv; q.w = e[4 * i + 3] * inv;
        pp[i] = q;
    }
    g_segpred[n] = am;
}

// K3: segment_min(point_ids, proposal_ids)
__global__ void k_segmin(const int* __restrict__ pid, const int* __restrict__ nid) {
    int m = blockIdx.x * blockDim.x + threadIdx.x;
    if (m >= NPAIR) return;
    atomicMin(&g_rep[pid[m]], nid[m]);
}

// K4: instance class per proposal
__global__ void k_inst() {
    int p = threadIdx.x;
    int r = g_rep[p];
    if (r > NPTS - 1) r = NPTS - 1;   // clip (handles empty: INT_MAX)
    g_inst[p] = g_segpred[r];
}

// K5: deduped scatter — counts + confidence score sums
__global__ void k_scatter(const int* __restrict__ pid, const int* __restrict__ nid,
                          const float* __restrict__ probs) {
    int m = blockIdx.x * blockDim.x + threadIdx.x;
    if (m >= NPAIR) return;
    int p = pid[m];
    int n = nid[m];
    size_t bit = (size_t)p * NPTS + n;
    unsigned int msk = 1u << (bit & 31u);
    unsigned int old = atomicOr(&g_bits[bit >> 5], msk);
    if (!(old & msk)) {
        atomicAdd(&g_count[p], 1);
        atomicAdd(&g_score[p], __ldg(&probs[(size_t)n * NCLS + g_inst[p]]));
    }
}

// K6: finalize scores / classes / flags
__global__ void k_finalize(float* __restrict__ out_scores, float* __restrict__ out_classes) {
    int p = threadIdx.x;
    int c = g_count[p];
    int flag = (c > THRESH) ? 1 : 0;
    g_flag[p] = flag;
    int cm = c > 1 ? c : 1;
    out_scores[p]  = flag ? (g_score[p] / (float)cm) : 0.0f;
    out_classes[p] = flag ? (float)g_inst[p] : -1.0f;
}

// K7: expand bitmask -> pred_masks (the big 204.8 MB write)
__global__ void k_write_masks(float* __restrict__ out_masks) {
    int t = blockIdx.x * blockDim.x + threadIdx.x;
    if (t >= (int)WORDS) return;
    int p = t / WPP;
    int j = t - p * WPP;
    unsigned int w = g_bits[t];
    if (!g_flag[p]) w = 0u;
    float4* dst = (float4*)(out_masks + (size_t)p * NPTS + (size_t)j * 32);
#pragma unroll
    for (int q = 0; q < 8; q++) {
        float4 f;
        f.x = (float)((w >> (4 * q + 0)) & 1u);
        f.y = (float)((w >> (4 * q + 1)) & 1u);
        f.z = (float)((w >> (4 * q + 2)) & 1u);
        f.w = (float)((w >> (4 * q + 3)) & 1u);
        dst[q] = f;
    }
}

extern "C" void kernel_launch(void* const* d_in, const int* in_sizes, int n_in,
                              void* d_out, int out_size) {
    const float* logit = (const float*)d_in[0];
    const float* bias  = (const float*)d_in[1];
    // d_in[2] = coord: dead (center_pred never returned)
    const int* pid = (const int*)d_in[3];
    const int* nid = (const int*)d_in[4];

    float* out = (float*)d_out;
    float* out_scores  = out + OFF_SCORES;
    float* out_masks   = out + OFF_MASKS;
    float* out_classes = out + OFF_CLASSES;
    float* out_bias    = out + OFF_BIAS;
    float* out_probs   = out + OFF_PROBS;

    const int B = 256;
    k_init<<<(int)((WORDS + B - 1) / B), B>>>(bias, out_bias);
    k_softmax<<<(NPTS + B - 1) / B, B>>>(logit, out_probs);
    k_segmin<<<(NPAIR + B - 1) / B, B>>>(pid, nid);
    k_inst<<<1, NPROP>>>();
    k_scatter<<<(NPAIR + B - 1) / B, B>>>(pid, nid, out_probs);
    k_finalize<<<1, NPROP>>>(out_scores, out_classes);
    k_write_masks<<<(int)((WORDS + B - 1) / B), B>>>(out_masks);
}

// round 4
// speedup vs baseline: 1.2022x; 1.2022x over previous
#include <cuda_runtime.h>
#include <cstdint>

// Problem constants (from reference)
#define NPTS 200000
#define NCLS 20
#define NPROP 256
#define NPAIR 400000
#define THRESH 100   // CLUSTER_PROPOSE_POINTS

// Derived
#define WPP (NPTS / 32)                 // 6250 words per proposal
#define WORDS ((size_t)NPROP * WPP)     // 1,600,000 words total (divisible by 32 and 256)

// Output layout (float32, concatenated in return order)
#define OFF_SCORES  ((size_t)0)
#define OFF_MASKS   ((size_t)256)
#define OFF_CLASSES ((size_t)(256 + (size_t)NPROP * NPTS))
#define OFF_BIAS    (OFF_CLASSES + 256)
#define OFF_PROBS   (OFF_BIAS + (size_t)NPTS * 3)

// Scratch (device globals: allocation-free)
__device__ unsigned int g_bits[WORDS];          // 6.4 MB dedupe bitmask
__device__ int   g_rep[NPROP];
__device__ int   g_count[NPROP];
__device__ float g_score[NPROP];
__device__ int   g_inst[NPROP];
__device__ int   g_flag[NPROP];
__device__ int   g_segpred[NPTS];

// K1: zero bitmask (uint4), init per-proposal scratch, copy bias passthrough (float4)
__global__ void k_init(const float* __restrict__ bias, float* __restrict__ bias_out) {
    size_t t = (size_t)blockIdx.x * blockDim.x + threadIdx.x;
    // zero bitmask: WORDS/4 = 400000 uint4 stores
    if (t < WORDS / 4) {
        ((uint4*)g_bits)[t] = make_uint4(0u, 0u, 0u, 0u);
    }
    if (t < NPROP) {
        g_rep[t]   = 0x7FFFFFFF;
        g_count[t] = 0;
        g_score[t] = 0.0f;
    }
    // bias copy: 600000 floats = 150000 float4
    if (t < (size_t)(NPTS * 3 / 4)) {
        ((float4*)bias_out)[t] = ((const float4*)bias)[t];
    }
}

// K2: per-block staged softmax + argmax (coalesced global traffic via smem)
__global__ void k_softmax(const float* __restrict__ logit,
                          float* __restrict__ probs_out) {
    __shared__ float s[256 * NCLS];   // 20 KB
    int tid  = threadIdx.x;
    int base = blockIdx.x * 256;
    int count = NPTS - base;
    if (count > 256) count = 256;

    // coalesced float4 load of this block's rows
    int nf4 = count * (NCLS / 4);     // count*5 float4s
    const float4* src = (const float4*)(logit + (size_t)base * NCLS);
    float4* s4 = (float4*)s;
    for (int i = tid; i < nf4; i += 256) s4[i] = src[i];
    __syncthreads();

    if (tid < count) {
        float* row = s + tid * NCLS;
        float v[NCLS];
#pragma unroll
        for (int i = 0; i < NCLS; i++) v[i] = row[i];
        float m = v[0]; int am = 0;
#pragma unroll
        for (int i = 1; i < NCLS; i++) {
            if (v[i] > m) { m = v[i]; am = i; }
        }
        float e[NCLS]; float sum = 0.0f;
#pragma unroll
        for (int i = 0; i < NCLS; i++) { e[i] = __expf(v[i] - m); sum += e[i]; }
        float inv = 1.0f / sum;
#pragma unroll
        for (int i = 0; i < NCLS; i++) row[i] = e[i] * inv;
        g_segpred[base + tid] = am;     // coalesced
    }
    __syncthreads();

    // coalesced float4 store of probs
    float4* dst = (float4*)(probs_out + (size_t)base * NCLS);
    for (int i = tid; i < nf4; i += 256) dst[i] = s4[i];
}

// K3: segment_min(point_ids, proposal_ids)
__global__ void k_segmin(const int* __restrict__ pid, const int* __restrict__ nid) {
    int m = blockIdx.x * blockDim.x + threadIdx.x;
    if (m >= NPAIR) return;
    atomicMin(&g_rep[pid[m]], nid[m]);
}

// K4: instance class per proposal
__global__ void k_inst() {
    int p = threadIdx.x;
    int r = g_rep[p];
    if (r > NPTS - 1) r = NPTS - 1;   // clip (handles empty: INT_MAX)
    g_inst[p] = g_segpred[r];
}

// K5: deduped scatter — counts + confidence score sums
__global__ void k_scatter(const int* __restrict__ pid, const int* __restrict__ nid,
                          const float* __restrict__ probs) {
    int m = blockIdx.x * blockDim.x + threadIdx.x;
    if (m >= NPAIR) return;
    int p = pid[m];
    int n = nid[m];
    size_t bit = (size_t)p * NPTS + n;
    unsigned int msk = 1u << (bit & 31u);
    unsigned int old = atomicOr(&g_bits[bit >> 5], msk);
    if (!(old & msk)) {
        atomicAdd(&g_count[p], 1);
        atomicAdd(&g_score[p], __ldg(&probs[(size_t)n * NCLS + g_inst[p]]));
    }
}

// K6: finalize scores / classes / flags
__global__ void k_finalize(float* __restrict__ out_scores, float* __restrict__ out_classes) {
    int p = threadIdx.x;
    int c = g_count[p];
    int flag = (c > THRESH) ? 1 : 0;
    g_flag[p] = flag;
    int cm = c > 1 ? c : 1;
    out_scores[p]  = flag ? (g_score[p] / (float)cm) : 0.0f;
    out_classes[p] = flag ? (float)g_inst[p] : -1.0f;
}

// K7: expand bitmask -> pred_masks (204.8 MB write), warp-coalesced stores.
// Output float address = word_index * 32 floats — globally contiguous in t.
// Each warp owns 32 words; lane pulls the word holding its 4 bits via shuffle,
// so every STG.128 is a fully coalesced 512B warp store.
__global__ void k_write_masks(float* __restrict__ out_masks) {
    int t = blockIdx.x * blockDim.x + threadIdx.x;   // word index, exact grid
    int lane = threadIdx.x & 31;
    unsigned int w = g_bits[t];
    if (!g_flag[t / WPP]) w = 0u;

    size_t warp_word0 = (size_t)(t - lane);
    float4* dst = (float4*)out_masks + warp_word0 * 8;   // 8 float4 per word
    int nib = (lane & 7) * 4;
#pragma unroll
    for (int i = 0; i < 8; i++) {
        unsigned int src = __shfl_sync(0xFFFFFFFFu, w, i * 4 + (lane >> 3));
        float4 f;
        f.x = (float)((src >> (nib + 0)) & 1u);
        f.y = (float)((src >> (nib + 1)) & 1u);
        f.z = (float)((src >> (nib + 2)) & 1u);
        f.w = (float)((src >> (nib + 3)) & 1u);
        dst[(size_t)i * 32 + lane] = f;
    }
}

extern "C" void kernel_launch(void* const* d_in, const int* in_sizes, int n_in,
                              void* d_out, int out_size) {
    const float* logit = (const float*)d_in[0];
    const float* bias  = (const float*)d_in[1];
    // d_in[2] = coord: dead (center_pred never returned)
    const int* pid = (const int*)d_in[3];
    const int* nid = (const int*)d_in[4];

    float* out = (float*)d_out;
    float* out_scores  = out + OFF_SCORES;
    float* out_masks   = out + OFF_MASKS;
    float* out_classes = out + OFF_CLASSES;
    float* out_bias    = out + OFF_BIAS;
    float* out_probs   = out + OFF_PROBS;

    const int B = 256;
    // init grid sized by the largest of its three jobs (bitmask/4 = 400000)
    k_init<<<(int)((WORDS / 4 + B - 1) / B), B>>>(bias, out_bias);
    k_softmax<<<(NPTS + 255) / 256, 256>>>(logit, out_probs);
    k_segmin<<<(NPAIR + B - 1) / B, B>>>(pid, nid);
    k_inst<<<1, NPROP>>>();
    k_scatter<<<(NPAIR + B - 1) / B, B>>>(pid, nid, out_probs);
    k_finalize<<<1, NPROP>>>(out_scores, out_classes);
    k_write_masks<<<(int)(WORDS / B), B>>>(out_masks);
}

// round 5
// speedup vs baseline: 5.1676x; 4.2984x over previous
#include <cuda_runtime.h>
#include <cstdint>

// Problem constants
#define NPTS 200000
#define NCLS 20
#define NPROP 256
#define NPAIR 400000
#define THRESH 100

// Derived
#define WPP (NPTS / 32)                 // 6250 words per proposal
#define WORDS ((size_t)NPROP * WPP)     // 1,600,000 words

// Output layout (float32, concatenated in return order)
#define OFF_SCORES  ((size_t)0)
#define OFF_MASKS   ((size_t)256)
#define OFF_CLASSES ((size_t)(256 + (size_t)NPROP * NPTS))
#define OFF_BIAS    (OFF_CLASSES + 256)
#define OFF_PROBS   (OFF_BIAS + (size_t)NPTS * 3)

#define PAD 32   // 128B stride between per-proposal counters (distinct L2 lines)

// Scratch (device globals: allocation-free)
__device__ unsigned int g_bits[WORDS];          // 6.4 MB dedupe bitmask
__device__ int   g_rep_p[NPROP * PAD];
__device__ int   g_count_p[NPROP * PAD];
__device__ float g_score_p[NPROP * PAD];
__device__ int   g_inst[NPROP];
__device__ int   g_segpred[NPTS];

// Fast exp: FMA-pipe only (no MUFU). Valid for x in ~[-80, 0]. rel err ~2e-6.
__device__ __forceinline__ float fexp(float x) {
    const float MAGIC = 12582912.0f;           // 1.5 * 2^23
    float t = fmaf(x, 1.4426950408889634f, MAGIC);
    int   n = __float_as_int(t) - 0x4B400000;  // round-to-nearest integer part
    float f = fmaf(x, 1.4426950408889634f, -(t - MAGIC));  // frac in [-0.5, 0.5]
    // 2^f, degree-5 Taylor in f*ln2
    float p = 1.3333558146e-3f;
    p = fmaf(p, f, 9.6181291076e-3f);
    p = fmaf(p, f, 5.5504108664e-2f);
    p = fmaf(p, f, 2.4022650696e-1f);
    p = fmaf(p, f, 6.9314718056e-1f);
    p = fmaf(p, f, 1.0f);
    return __int_as_float(__float_as_int(p) + (n << 23));
}

// K1: zero bitmask, init padded scratch, copy bias passthrough
__global__ void k_init(const float* __restrict__ bias, float* __restrict__ bias_out) {
    size_t t = (size_t)blockIdx.x * blockDim.x + threadIdx.x;
    if (t < WORDS / 4) ((uint4*)g_bits)[t] = make_uint4(0u, 0u, 0u, 0u);
    if (t < NPROP * PAD) {
        g_rep_p[t]   = 0x7FFFFFFF;
        g_count_p[t] = 0;
        g_score_p[t] = 0.0f;
    }
    if (t < (size_t)(NPTS * 3 / 4)) {
        ((float4*)bias_out)[t] = ((const float4*)bias)[t];
    }
}

// K2: staged softmax + argmax. Padded smem rows (21 floats: conflict-free),
// coalesced scalar global traffic, FMA-pipe exp.
__global__ void k_softmax(const float* __restrict__ logit,
                          float* __restrict__ probs_out) {
    __shared__ float s[256 * 21];   // 21 KB
    int tid  = threadIdx.x;
    int base = blockIdx.x * 256;
    int count = NPTS - base;
    if (count > 256) count = 256;
    int tot = count * NCLS;

    const float* src = logit + (size_t)base * NCLS;
    for (int i = tid; i < tot; i += 256) {
        int row = i / NCLS, col = i - row * NCLS;
        s[row * 21 + col] = src[i];
    }
    __syncthreads();

    if (tid < count) {
        float* row = s + tid * 21;
        float v[NCLS];
#pragma unroll
        for (int i = 0; i < NCLS; i++) v[i] = row[i];
        float m = v[0]; int am = 0;
#pragma unroll
        for (int i = 1; i < NCLS; i++) if (v[i] > m) { m = v[i]; am = i; }
        float e[NCLS]; float sum = 0.0f;
#pragma unroll
        for (int i = 0; i < NCLS; i++) { e[i] = fexp(v[i] - m); sum += e[i]; }
        float inv = 1.0f / sum;
#pragma unroll
        for (int i = 0; i < NCLS; i++) row[i] = e[i] * inv;
        g_segpred[base + tid] = am;
    }
    __syncthreads();

    float* dst = probs_out + (size_t)base * NCLS;
    for (int i = tid; i < tot; i += 256) {
        int row = i / NCLS, col = i - row * NCLS;
        dst[i] = s[row * 21 + col];
    }
}

// K3: segment_min with smem privatization, flush to padded global
__global__ void k_segmin(const int* __restrict__ pid, const int* __restrict__ nid) {
    __shared__ int sm[NPROP];
    int tid = threadIdx.x;
    for (int i = tid; i < NPROP; i += blockDim.x) sm[i] = 0x7FFFFFFF;
    __syncthreads();
    int stride = gridDim.x * blockDim.x;
    for (int m = blockIdx.x * blockDim.x + tid; m < NPAIR; m += stride)
        atomicMin(&sm[pid[m]], nid[m]);
    __syncthreads();
    for (int i = tid; i < NPROP; i += blockDim.x)
        if (sm[i] != 0x7FFFFFFF) atomicMin(&g_rep_p[i * PAD], sm[i]);
}

// K4: deduped scatter. Per-block smem: inst cache + count/score histograms.
// Global: atomicOr bitmask (spread over 6.4MB), padded flush at the end.
__global__ void k_scatter(const int* __restrict__ pid, const int* __restrict__ nid,
                          const float* __restrict__ probs) {
    __shared__ int   s_inst[NPROP];
    __shared__ int   s_cnt[NPROP];
    __shared__ float s_scr[NPROP];
    int tid = threadIdx.x;
    for (int i = tid; i < NPROP; i += blockDim.x) {
        int r = g_rep_p[i * PAD];
        if (r > NPTS - 1) r = NPTS - 1;
        s_inst[i] = g_segpred[r];
        s_cnt[i] = 0;
        s_scr[i] = 0.0f;
    }
    if (blockIdx.x == 0)
        for (int i = tid; i < NPROP; i += blockDim.x) g_inst[i] = s_inst[i];
    __syncthreads();

    int stride = gridDim.x * blockDim.x;
    for (int m = blockIdx.x * blockDim.x + tid; m < NPAIR; m += stride) {
        int p = pid[m];
        int n = nid[m];
        size_t bit = (size_t)p * NPTS + n;
        unsigned int msk = 1u << (bit & 31u);
        unsigned int old = atomicOr(&g_bits[bit >> 5], msk);
        if (!(old & msk)) {
            atomicAdd(&s_cnt[p], 1);
            atomicAdd(&s_scr[p], __ldg(&probs[(size_t)n * NCLS + s_inst[p]]));
        }
    }
    __syncthreads();
    for (int i = tid; i < NPROP; i += blockDim.x) {
        if (s_cnt[i]) {
            atomicAdd(&g_count_p[i * PAD], s_cnt[i]);
            atomicAdd(&g_score_p[i * PAD], s_scr[i]);
        }
    }
}

// K5: mask expansion (warp-coalesced 512B stores) + fused finalize in block 0
__global__ void k_masks_final(float* __restrict__ out_masks,
                              float* __restrict__ out_scores,
                              float* __restrict__ out_classes) {
    int tid = threadIdx.x;
    if (blockIdx.x == 0 && tid < NPROP) {
        int c = g_count_p[tid * PAD];
        int flag = (c > THRESH) ? 1 : 0;
        int cm = c > 1 ? c : 1;
        out_scores[tid]  = flag ? (g_score_p[tid * PAD] / (float)cm) : 0.0f;
        out_classes[tid] = flag ? (float)g_inst[tid] : -1.0f;
    }

    int t = blockIdx.x * blockDim.x + tid;   // word index (exact grid)
    int lane = tid & 31;
    int p = t / WPP;
    unsigned int w = g_bits[t];
    if (g_count_p[p * PAD] <= THRESH) w = 0u;

    size_t warp_word0 = (size_t)(t - lane);
    float4* dst = (float4*)out_masks + warp_word0 * 8;   // 8 float4 per word
    int nib = (lane & 7) * 4;
#pragma unroll
    for (int i = 0; i < 8; i++) {
        unsigned int src = __shfl_sync(0xFFFFFFFFu, w, i * 4 + (lane >> 3));
        float4 f;
        f.x = (float)((src >> (nib + 0)) & 1u);
        f.y = (float)((src >> (nib + 1)) & 1u);
        f.z = (float)((src >> (nib + 2)) & 1u);
        f.w = (float)((src >> (nib + 3)) & 1u);
        dst[(size_t)i * 32 + lane] = f;
    }
}

extern "C" void kernel_launch(void* const* d_in, const int* in_sizes, int n_in,
                              void* d_out, int out_size) {
    const float* logit = (const float*)d_in[0];
    const float* bias  = (const float*)d_in[1];
    // d_in[2] = coord: dead (center_pred never returned)
    const int* pid = (const int*)d_in[3];
    const int* nid = (const int*)d_in[4];

    float* out = (float*)d_out;
    float* out_scores  = out + OFF_SCORES;
    float* out_masks   = out + OFF_MASKS;
    float* out_classes = out + OFF_CLASSES;
    float* out_bias    = out + OFF_BIAS;
    float* out_probs   = out + OFF_PROBS;

    k_init<<<(int)((WORDS / 4 + 255) / 256), 256>>>(bias, out_bias);
    k_softmax<<<(NPTS + 255) / 256, 256>>>(logit, out_probs);
    k_segmin<<<148, 512>>>(pid, nid);
    k_scatter<<<296, 256>>>(pid, nid, out_probs);
    k_masks_final<<<(int)(WORDS / 256), 256>>>(out_masks, out_scores, out_classes);
}

// round 6
// speedup vs baseline: 5.6865x; 1.1004x over previous
#include <cuda_runtime.h>
#include <cstdint>

// Problem constants
#define NPTS 200000
#define NCLS 20
#define NPROP 256
#define NPAIR 400000
#define THRESH 100

// Derived
#define WPP (NPTS / 32)                 // 6250 words per proposal
#define WORDS ((size_t)NPROP * WPP)     // 1,600,000 words

// Output layout (float32, concatenated in return order)
#define OFF_SCORES  ((size_t)0)
#define OFF_MASKS   ((size_t)256)
#define OFF_CLASSES ((size_t)(256 + (size_t)NPROP * NPTS))
#define OFF_BIAS    (OFF_CLASSES + 256)
#define OFF_PROBS   (OFF_BIAS + (size_t)NPTS * 3)

#define PAD 32   // 128B stride between per-proposal counters (distinct L2 lines)

// Scratch (device globals: allocation-free)
__device__ unsigned int g_bits[WORDS];          // 6.4 MB dedupe bitmask
__device__ int   g_rep_p[NPROP * PAD];
__device__ int   g_count_p[NPROP * PAD];
__device__ float g_score_p[NPROP * PAD];
__device__ int   g_inst[NPROP];
__device__ int   g_segpred[NPTS];

// Fast exp on FMA pipe (no MUFU). rel err ~2e-6.
__device__ __forceinline__ float fexp(float x) {
    const float MAGIC = 12582912.0f;           // 1.5 * 2^23
    float t = fmaf(x, 1.4426950408889634f, MAGIC);
    int   n = __float_as_int(t) - 0x4B400000;
    float f = fmaf(x, 1.4426950408889634f, -(t - MAGIC));
    float p = 1.3333558146e-3f;
    p = fmaf(p, f, 9.6181291076e-3f);
    p = fmaf(p, f, 5.5504108664e-2f);
    p = fmaf(p, f, 2.4022650696e-1f);
    p = fmaf(p, f, 6.9314718056e-1f);
    p = fmaf(p, f, 1.0f);
    return __int_as_float(__float_as_int(p) + (n << 23));
}

// --- stream A: zero bitmask ---
__global__ void k_zero_bits() {
    size_t t = (size_t)blockIdx.x * blockDim.x + threadIdx.x;
    if (t < WORDS / 4) ((uint4*)g_bits)[t] = make_uint4(0u, 0u, 0u, 0u);
}

// --- stream C: init padded counters (before segmin/scatter) ---
__global__ void k_init_small() {
    int t = blockIdx.x * blockDim.x + threadIdx.x;
    if (t < NPROP * PAD) {
        g_rep_p[t]   = 0x7FFFFFFF;
        g_count_p[t] = 0;
        g_score_p[t] = 0.0f;
    }
}

// --- side stream: bias passthrough (overlaps scatter/masks) ---
__global__ void k_bias(const float* __restrict__ bias, float* __restrict__ bias_out) {
    int t = blockIdx.x * blockDim.x + threadIdx.x;
    if (t < NPTS * 3 / 4) ((float4*)bias_out)[t] = ((const float4*)bias)[t];
}

// --- stream B: staged softmax + argmax (padded smem rows, FMA exp) ---
__global__ void k_softmax(const float* __restrict__ logit,
                          float* __restrict__ probs_out) {
    __shared__ float s[256 * 21];   // 21 KB
    int tid  = threadIdx.x;
    int base = blockIdx.x * 256;
    int count = NPTS - base;
    if (count > 256) count = 256;
    int tot = count * NCLS;

    const float* src = logit + (size_t)base * NCLS;
    for (int i = tid; i < tot; i += 256) {
        int row = i / NCLS, col = i - row * NCLS;
        s[row * 21 + col] = src[i];
    }
    __syncthreads();

    if (tid < count) {
        float* row = s + tid * 21;
        float v[NCLS];
#pragma unroll
        for (int i = 0; i < NCLS; i++) v[i] = row[i];
        float m = v[0]; int am = 0;
#pragma unroll
        for (int i = 1; i < NCLS; i++) if (v[i] > m) { m = v[i]; am = i; }
        float e[NCLS]; float sum = 0.0f;
#pragma unroll
        for (int i = 0; i < NCLS; i++) { e[i] = fexp(v[i] - m); sum += e[i]; }
        float inv = 1.0f / sum;
#pragma unroll
        for (int i = 0; i < NCLS; i++) row[i] = e[i] * inv;
        g_segpred[base + tid] = am;
    }
    __syncthreads();

    float* dst = probs_out + (size_t)base * NCLS;
    for (int i = tid; i < tot; i += 256) {
        int row = i / NCLS, col = i - row * NCLS;
        dst[i] = s[row * 21 + col];
    }
}

// --- stream C: segment_min via smem privatization ---
__global__ void k_segmin(const int* __restrict__ pid, const int* __restrict__ nid) {
    __shared__ int sm[NPROP];
    int tid = threadIdx.x;
    for (int i = tid; i < NPROP; i += blockDim.x) sm[i] = 0x7FFFFFFF;
    __syncthreads();
    int stride = gridDim.x * blockDim.x;
    for (int m = blockIdx.x * blockDim.x + tid; m < NPAIR; m += stride)
        atomicMin(&sm[pid[m]], nid[m]);
    __syncthreads();
    for (int i = tid; i < NPROP; i += blockDim.x)
        if (sm[i] != 0x7FFFFFFF) atomicMin(&g_rep_p[i * PAD], sm[i]);
}

// --- joined: deduped scatter, block=1024 for full occupancy ---
__global__ void __launch_bounds__(1024, 2)
k_scatter(const int* __restrict__ pid, const int* __restrict__ nid,
          const float* __restrict__ probs) {
    __shared__ int   s_inst[NPROP];
    __shared__ int   s_cnt[NPROP];
    __shared__ float s_scr[NPROP];
    int tid = threadIdx.x;
    if (tid < NPROP) {
        int r = g_rep_p[tid * PAD];
        if (r > NPTS - 1) r = NPTS - 1;
        int inst = g_segpred[r];
        s_inst[tid] = inst;
        s_cnt[tid] = 0;
        s_scr[tid] = 0.0f;
        if (blockIdx.x == 0) g_inst[tid] = inst;
    }
    __syncthreads();

    int stride = gridDim.x * blockDim.x;
    for (int m = blockIdx.x * blockDim.x + tid; m < NPAIR; m += stride) {
        int p = pid[m];
        int n = nid[m];
        size_t bit = (size_t)p * NPTS + n;
        unsigned int msk = 1u << (bit & 31u);
        unsigned int old = atomicOr(&g_bits[bit >> 5], msk);
        if (!(old & msk)) {
            atomicAdd(&s_cnt[p], 1);
            atomicAdd(&s_scr[p], __ldg(&probs[(size_t)n * NCLS + s_inst[p]]));
        }
    }
    __syncthreads();
    if (tid < NPROP) {
        if (s_cnt[tid]) {
            atomicAdd(&g_count_p[tid * PAD], s_cnt[tid]);
            atomicAdd(&g_score_p[tid * PAD], s_scr[tid]);
        }
    }
}

// --- mask expansion (warp-coalesced 512B stores) + fused finalize in block 0 ---
__global__ void k_masks_final(float* __restrict__ out_masks,
                              float* __restrict__ out_scores,
                              float* __restrict__ out_classes) {
    int tid = threadIdx.x;
    if (blockIdx.x == 0 && tid < NPROP) {
        int c = g_count_p[tid * PAD];
        int flag = (c > THRESH) ? 1 : 0;
        int cm = c > 1 ? c : 1;
        out_scores[tid]  = flag ? (g_score_p[tid * PAD] / (float)cm) : 0.0f;
        out_classes[tid] = flag ? (float)g_inst[tid] : -1.0f;
    }

    int t = blockIdx.x * blockDim.x + tid;   // word index (exact grid)
    int lane = tid & 31;
    int p = t / WPP;
    unsigned int w = g_bits[t];
    if (g_count_p[p * PAD] <= THRESH) w = 0u;

    size_t warp_word0 = (size_t)(t - lane);
    float4* dst = (float4*)out_masks + warp_word0 * 8;   // 8 float4 per word
    int nib = (lane & 7) * 4;
#pragma unroll
    for (int i = 0; i < 8; i++) {
        unsigned int src = __shfl_sync(0xFFFFFFFFu, w, i * 4 + (lane >> 3));
        float4 f;
        f.x = (float)((src >> (nib + 0)) & 1u);
        f.y = (float)((src >> (nib + 1)) & 1u);
        f.z = (float)((src >> (nib + 2)) & 1u);
        f.w = (float)((src >> (nib + 3)) & 1u);
        dst[(size_t)i * 32 + lane] = f;
    }
}

extern "C" void kernel_launch(void* const* d_in, const int* in_sizes, int n_in,
                              void* d_out, int out_size) {
    const float* logit = (const float*)d_in[0];
    const float* bias  = (const float*)d_in[1];
    // d_in[2] = coord: dead (center_pred never returned)
    const int* pid = (const int*)d_in[3];
    const int* nid = (const int*)d_in[4];

    float* out = (float*)d_out;
    float* out_scores  = out + OFF_SCORES;
    float* out_masks   = out + OFF_MASKS;
    float* out_classes = out + OFF_CLASSES;
    float* out_bias    = out + OFF_BIAS;
    float* out_probs   = out + OFF_PROBS;

    // Lazily created once; reused every call (same work each call — deterministic).
    static cudaStream_t sB = nullptr, sC = nullptr, sD = nullptr;
    static cudaEvent_t eRoot, eB, eC, eD;
    if (!sB) {
        cudaStreamCreateWithFlags(&sB, cudaStreamNonBlocking);
        cudaStreamCreateWithFlags(&sC, cudaStreamNonBlocking);
        cudaStreamCreateWithFlags(&sD, cudaStreamNonBlocking);
        cudaEventCreateWithFlags(&eRoot, cudaEventDisableTiming);
        cudaEventCreateWithFlags(&eB, cudaEventDisableTiming);
        cudaEventCreateWithFlags(&eC, cudaEventDisableTiming);
        cudaEventCreateWithFlags(&eD, cudaEventDisableTiming);
    }

    // fork
    cudaEventRecord(eRoot, 0);
    cudaStreamWaitEvent(sB, eRoot, 0);
    cudaStreamWaitEvent(sC, eRoot, 0);
    cudaStreamWaitEvent(sD, eRoot, 0);

    // stream 0: zero bitmask
    k_zero_bits<<<(int)((WORDS / 4 + 255) / 256), 256>>>();
    // stream B: softmax (+probs, segpred)
    k_softmax<<<(NPTS + 255) / 256, 256, 0, sB>>>(logit, out_probs);
    // stream C: counter init -> segmin
    k_init_small<<<(NPROP * PAD + 255) / 256, 256, 0, sC>>>();
    k_segmin<<<148, 512, 0, sC>>>(pid, nid);
    // stream D: bias passthrough (fully independent)
    k_bias<<<(NPTS * 3 / 4 + 255) / 256, 256, 0, sD>>>(bias, out_bias);

    // join B and C into stream 0 before scatter
    cudaEventRecord(eB, sB);
    cudaEventRecord(eC, sC);
    cudaStreamWaitEvent(0, eB, 0);
    cudaStreamWaitEvent(0, eC, 0);

    k_scatter<<<296, 1024>>>(pid, nid, out_probs);
    k_masks_final<<<(int)(WORDS / 256), 256>>>(out_masks, out_scores, out_classes);

    // join D at the very end
    cudaEventRecord(eD, sD);
    cudaStreamWaitEvent(0, eD, 0);
}